// round 4
// baseline (speedup 1.0000x reference)
#include <cuda_runtime.h>

// out = tanh(in @ Lr^T + br) + in @ Ld^T + bd + in
// Lr[n,m] = delta(n==m)*cs_r[n] - Wr[n,m],  Wr[ei,ej] += wr, cs_r[n]=sum_{ej=n} wr
// Ld[n,m] = delta(n==m)*cs_d[n] - Wd[n,m],  Wd[ej,ei] += wd, cs_d[n]=sum_{ei=n} wd
//
// Store S[m][n] = (G,H) interleaved, G[m][n]=Lr[n][m], H[m][n]=Ld[n][m]:
//   edge (i,j,wr,wd):  G[j][i] -= wr; G[j][j] += wr;  H[i][j] -= wd; H[i][i] += wd;
// reaction[b,n] = sum_m in[b,m]*G[m][n]; diffusion[b,n] = sum_m in[b,m]*H[m][n].
//
// Single fused kernel: row-owner build (smem) -> grid barrier -> GEMM.

#define NN 207
#define NE 1722
#define BATCH 64
#define GRID 128            // 64 batches x 2 column halves; all-resident (<=148 SMs)
#define THREADS 256
#define ROWS_PER_CTA 2      // 128*2 = 256 >= 207 rows
#define PITCH (2 * NN)      // 414 floats per S-row (interleaved G,H)
#define HALF 104            // columns per GEMM half (2*104 >= 207)

__device__ __align__(16) float g_S[NN * PITCH];
__device__ unsigned g_count = 0;
__device__ volatile unsigned g_epoch = 0;

__device__ __forceinline__ void grid_barrier() {
    __syncthreads();
    if (threadIdx.x == 0) {
        __threadfence();                       // make this CTA's g_S stores visible
        const unsigned e = g_epoch;            // snapshot before arriving
        if (atomicAdd(&g_count, 1u) == GRID - 1u) {
            g_count = 0;                       // safe: all CTAs have arrived
            __threadfence();
            g_epoch = e + 1u;                  // release
        } else {
            while (g_epoch == e) { __nanosleep(64); }
        }
        __threadfence();                       // acquire
    }
    __syncthreads();
}

__global__ __launch_bounds__(THREADS)
void fused_k(const float* __restrict__ in,
             const float* __restrict__ wr,
             const float* __restrict__ wd,
             const float* __restrict__ br,
             const float* __restrict__ bd,
             const int*   __restrict__ ei,
             const int*   __restrict__ ej,
             float* __restrict__ out) {
    __shared__ float s_tile[ROWS_PER_CTA * PITCH];
    __shared__ float s_in[NN];

    const int tid   = threadIdx.x;
    const int bid   = blockIdx.x;
    const int batch = bid >> 1;
    const int half  = bid & 1;
    const int row_lo = bid * ROWS_PER_CTA;     // CTAs 0..103 own rows; 104..127 own none

    // ---------- phase A: build owned S rows in smem ----------
    #pragma unroll 2
    for (int x = tid; x < ROWS_PER_CTA * PITCH; x += THREADS) s_tile[x] = 0.0f;
    if (tid < NN) s_in[tid] = in[batch * NN + tid];   // THREADS >= NN
    __syncthreads();

    if (row_lo < NN) {
        for (int k = tid; k < NE; k += THREADS) {
            const int i = ei[k];
            const int j = ej[k];
            const int jl = j - row_lo;
            if ((unsigned)jl < (unsigned)ROWS_PER_CTA) {       // reaction rows: m = j
                const float vr = wr[k];
                atomicAdd(&s_tile[jl * PITCH + 2 * i],     -vr);
                atomicAdd(&s_tile[jl * PITCH + 2 * j],      vr);
            }
            const int il = i - row_lo;
            if ((unsigned)il < (unsigned)ROWS_PER_CTA) {       // diffusion rows: m = i
                const float vd = wd[k];
                atomicAdd(&s_tile[il * PITCH + 2 * j + 1], -vd);
                atomicAdd(&s_tile[il * PITCH + 2 * i + 1],  vd);
            }
        }
    }
    __syncthreads();

    if (row_lo < NN) {
        const int nfl = min(ROWS_PER_CTA, NN - row_lo) * PITCH;
        float* dst = &g_S[row_lo * PITCH];
        for (int x = tid; x < nfl; x += THREADS) dst[x] = s_tile[x];
    }

    // ---------- barrier: all S rows visible chip-wide ----------
    grid_barrier();

    // ---------- phase B: GEMM + epilogue ----------
    if (tid < HALF) {
        const int n = half * HALF + tid;
        if (n < NN) {
            const float2* __restrict__ S2 = reinterpret_cast<const float2*>(g_S);
            float ar = 0.0f, ad = 0.0f;
            #pragma unroll 8
            for (int m = 0; m < NN; m++) {
                const float2 gh = __ldcg(&S2[m * NN + n]);  // L2 (bypass possibly-stale L1)
                const float x = s_in[m];
                ar = fmaf(x, gh.x, ar);
                ad = fmaf(x, gh.y, ad);
            }
            out[batch * NN + n] = tanhf(ar + br[n]) + ad + bd[n] + s_in[n];
        }
    }
}

extern "C" void kernel_launch(void* const* d_in, const int* in_sizes, int n_in,
                              void* d_out, int out_size) {
    const float* in_ = (const float*)d_in[0];
    const float* wr  = (const float*)d_in[1];
    const float* wd  = (const float*)d_in[2];
    const float* br  = (const float*)d_in[3];
    const float* bd  = (const float*)d_in[4];
    const int*   ei  = (const int*)d_in[5];
    const int*   ej  = (const int*)d_in[6];
    float* out = (float*)d_out;

    fused_k<<<GRID, THREADS>>>(in_, wr, wd, br, bd, ei, ej, out);
}

// round 5
// speedup vs baseline: 2.9286x; 2.9286x over previous
#include <cuda_runtime.h>
#include <cstdint>

// out = tanh(in @ Lr^T + br) + in @ Ld^T + bd + in
// Edge-flow scatter form (see R2):
//   per edge k: vr = wr_k*in[ej]; r[ej]+=vr; r[ei]-=vr;
//               vd = wd_k*in[ei]; d[ei]+=vd; d[ej]-=vd;
// Cluster-of-2 per batch: each CTA scatters half the edges into its own smem
// partials; hardware cluster barrier; combine via DSMEM; epilogue.

#define NN 207
#define NE 1722
#define BATCH 64
#define THREADS 256
#define HALF_E (NE / 2)          // 861
#define N0_HALF 104              // rank0 nodes [0,104), rank1 [104,207)

__device__ __forceinline__ uint32_t smem_u32(const void* p) {
    uint32_t a;
    asm("{ .reg .u64 t; cvta.to.shared.u64 t, %1; cvt.u32.u64 %0, t; }"
        : "=r"(a) : "l"(p));
    return a;
}

__global__ __launch_bounds__(THREADS) __cluster_dims__(2, 1, 1)
void rd_cluster_k(const float* __restrict__ in,
                  const float* __restrict__ wr,
                  const float* __restrict__ wd,
                  const float* __restrict__ br,
                  const float* __restrict__ bd,
                  const int*   __restrict__ ei,
                  const int*   __restrict__ ej,
                  float* __restrict__ out) {
    __shared__ float  s_in[NN];
    __shared__ float2 s_rd[NN];          // (reaction, diffusion) partials

    const int tid   = threadIdx.x;
    const int batch = blockIdx.x >> 1;
    uint32_t rank;
    asm("mov.u32 %0, %%cluster_ctarank;" : "=r"(rank));

    // load input row + zero partials (THREADS >= NN)
    if (tid < NN) {
        s_in[tid] = in[batch * NN + tid];
        s_rd[tid] = make_float2(0.0f, 0.0f);
    }
    __syncthreads();

    // scatter my half of the edges (smem atomics)
    const int k0 = (int)rank * HALF_E;
    for (int k = k0 + tid; k < k0 + HALF_E; k += THREADS) {
        const int i = ei[k];
        const int j = ej[k];
        const float vr = wr[k] * s_in[j];
        atomicAdd(&s_rd[j].x,  vr);
        atomicAdd(&s_rd[i].x, -vr);
        const float vd = wd[k] * s_in[i];
        atomicAdd(&s_rd[i].y,  vd);
        atomicAdd(&s_rd[j].y, -vd);
    }
    __syncthreads();                      // drain this CTA's smem atomics

    // hardware cluster barrier: both CTAs' partials complete & visible
    asm volatile("barrier.cluster.arrive.aligned;" ::: "memory");
    asm volatile("barrier.cluster.wait.aligned;"   ::: "memory");

    // combine + epilogue: rank0 -> nodes [0,104), rank1 -> [104,207)
    const int n_base = rank ? N0_HALF : 0;
    const int n_cnt  = rank ? (NN - N0_HALF) : N0_HALF;
    if (tid < n_cnt) {
        const int n = n_base + tid;
        const float2 own = s_rd[n];

        uint32_t la = smem_u32(&s_rd[n]);
        uint32_t pa;
        asm("mapa.shared::cluster.u32 %0, %1, %2;"
            : "=r"(pa) : "r"(la), "r"(rank ^ 1u));
        float pr, pd;
        asm volatile("ld.shared::cluster.v2.f32 {%0, %1}, [%2];"
                     : "=f"(pr), "=f"(pd) : "r"(pa));

        const float r = own.x + pr + br[n];
        const float d = own.y + pd + bd[n];
        out[batch * NN + n] = tanhf(r) + d + bd[n] - bd[n] + s_in[n] + 0.0f * 0.0f
                              ;
        // (single expression kept simple below instead)
        out[batch * NN + n] = tanhf(r) + d + s_in[n];
    }

    // keep SMEM alive until the peer finished its DSMEM reads
    asm volatile("barrier.cluster.arrive.aligned;" ::: "memory");
    asm volatile("barrier.cluster.wait.aligned;"   ::: "memory");
}

extern "C" void kernel_launch(void* const* d_in, const int* in_sizes, int n_in,
                              void* d_out, int out_size) {
    const float* in_ = (const float*)d_in[0];
    const float* wr  = (const float*)d_in[1];
    const float* wd  = (const float*)d_in[2];
    const float* br  = (const float*)d_in[3];
    const float* bd  = (const float*)d_in[4];
    const int*   ei  = (const int*)d_in[5];
    const int*   ej  = (const int*)d_in[6];
    float* out = (float*)d_out;

    rd_cluster_k<<<BATCH * 2, THREADS>>>(in_, wr, wd, br, bd, ei, ej, out);
}

// round 6
// speedup vs baseline: 3.6176x; 1.2353x over previous
#include <cuda_runtime.h>
#include <cstdint>

// out = tanh(in @ Lr^T + br) + in @ Ld^T + bd + in
// Edge-flow scatter:
//   per edge k: vr = wr_k*in[ej]; r[ej]+=vr; r[ei]-=vr;
//               vd = wd_k*in[ei]; d[ei]+=vd; d[ej]-=vd;
// Cluster-of-2 per batch: each CTA scatters its half of the edges into its own
// smem partials (vectorized 2-edge prefetch per thread), hardware cluster
// barrier, DSMEM combine, epilogue.

#define NN 207
#define NE 1722
#define BATCH 64
#define THREADS 512
#define SPLIT 864               // rank0 edges [0,864), rank1 [864,1722); both 8B-aligned
#define N0_HALF 104             // rank0 epilogue nodes [0,104), rank1 [104,207)

__device__ __forceinline__ uint32_t smem_u32(const void* p) {
    uint32_t a;
    asm("{ .reg .u64 t; cvta.to.shared.u64 t, %1; cvt.u32.u64 %0, t; }"
        : "=r"(a) : "l"(p));
    return a;
}

__global__ __launch_bounds__(THREADS) __cluster_dims__(2, 1, 1)
void rd_cluster_k(const float* __restrict__ in,
                  const float* __restrict__ wr,
                  const float* __restrict__ wd,
                  const float* __restrict__ br,
                  const float* __restrict__ bd,
                  const int*   __restrict__ ei,
                  const int*   __restrict__ ej,
                  float* __restrict__ out) {
    __shared__ float  s_in[NN];
    __shared__ float2 s_rd[NN];          // (reaction, diffusion) partials

    const int tid   = threadIdx.x;
    const int batch = blockIdx.x >> 1;
    uint32_t rank;
    asm("mov.u32 %0, %%cluster_ctarank;" : "=r"(rank));

    // ---- prefetch my 2 edges (4 x LDG.64, high MLP) ----
    const int base  = rank ? SPLIT : 0;
    const int cnt   = rank ? (NE - SPLIT) : SPLIT;   // 858 / 864, both even
    const int pairs = cnt >> 1;                       // 429 / 432 (< THREADS)
    int2 ii, jj; float2 wrr, wdd;
    const bool has_edges = (tid < pairs);
    if (has_edges) {
        const int k = base + 2 * tid;
        ii  = *reinterpret_cast<const int2*>(&ei[k]);
        jj  = *reinterpret_cast<const int2*>(&ej[k]);
        wrr = *reinterpret_cast<const float2*>(&wr[k]);
        wdd = *reinterpret_cast<const float2*>(&wd[k]);
    }

    // ---- load input row + zero partials ----
    if (tid < NN) {
        s_in[tid] = in[batch * NN + tid];
        s_rd[tid] = make_float2(0.0f, 0.0f);
    }
    __syncthreads();

    // ---- scatter (smem atomics) ----
    if (has_edges) {
        {
            const int i = ii.x, j = jj.x;
            const float vr = wrr.x * s_in[j];
            const float vd = wdd.x * s_in[i];
            atomicAdd(&s_rd[j].x,  vr);
            atomicAdd(&s_rd[i].x, -vr);
            atomicAdd(&s_rd[i].y,  vd);
            atomicAdd(&s_rd[j].y, -vd);
        }
        {
            const int i = ii.y, j = jj.y;
            const float vr = wrr.y * s_in[j];
            const float vd = wdd.y * s_in[i];
            atomicAdd(&s_rd[j].x,  vr);
            atomicAdd(&s_rd[i].x, -vr);
            atomicAdd(&s_rd[i].y,  vd);
            atomicAdd(&s_rd[j].y, -vd);
        }
    }
    __syncthreads();                      // drain this CTA's smem atomics

    // ---- hardware cluster barrier: both CTAs' partials complete ----
    asm volatile("barrier.cluster.arrive.aligned;" ::: "memory");
    asm volatile("barrier.cluster.wait.aligned;"   ::: "memory");

    // ---- combine + epilogue ----
    const int n_base = rank ? N0_HALF : 0;
    const int n_cnt  = rank ? (NN - N0_HALF) : N0_HALF;
    if (tid < n_cnt) {
        const int n = n_base + tid;
        const float2 own = s_rd[n];

        uint32_t la = smem_u32(&s_rd[n]);
        uint32_t pa;
        asm("mapa.shared::cluster.u32 %0, %1, %2;"
            : "=r"(pa) : "r"(la), "r"(rank ^ 1u));
        float pr, pd;
        asm volatile("ld.shared::cluster.v2.f32 {%0, %1}, [%2];"
                     : "=f"(pr), "=f"(pd) : "r"(pa));

        const float r = own.x + pr + br[n];
        const float d = own.y + pd + bd[n];
        out[batch * NN + n] = tanhf(r) + d + s_in[n];
    }

    // keep SMEM alive until the peer finished its DSMEM reads
    asm volatile("barrier.cluster.arrive.aligned;" ::: "memory");
    asm volatile("barrier.cluster.wait.aligned;"   ::: "memory");
}

extern "C" void kernel_launch(void* const* d_in, const int* in_sizes, int n_in,
                              void* d_out, int out_size) {
    const float* in_ = (const float*)d_in[0];
    const float* wr  = (const float*)d_in[1];
    const float* wd  = (const float*)d_in[2];
    const float* br  = (const float*)d_in[3];
    const float* bd  = (const float*)d_in[4];
    const int*   ei  = (const int*)d_in[5];
    const int*   ej  = (const int*)d_in[6];
    float* out = (float*)d_out;

    rd_cluster_k<<<BATCH * 2, THREADS>>>(in_, wr, wd, br, bd, ei, ej, out);
}